// round 5
// baseline (speedup 1.0000x reference)
#include <cuda_runtime.h>
#include <cuda_bf16.h>
#include <math.h>

// Problem constants (fixed by the reference setup).
#define NNODES 100000
#define NEDGES 1600000
#define F_IN   256
#define F_HID  128
#define F_OUT  40

// ---------------------------------------------------------------------------
// Scratch (device globals; no cudaMalloc allowed)
// ---------------------------------------------------------------------------
__device__ float g_h [NNODES * F_HID];   // GEMM output (also reused, stride 40, for layer 3)
__device__ float g_x0[NNODES * F_HID];   // x0 (residual)
__device__ float g_xa[NNODES * F_HID];   // x1
__device__ float g_xb[NNODES * F_HID];   // x2
__device__ int   g_deg   [NNODES];
__device__ int   g_rowptr[NNODES + 1];
__device__ int   g_cursor[NNODES];
__device__ int2  g_esw   [NEDGES];       // (src, bits(edge_weight)) sorted by tgt

// ---------------------------------------------------------------------------
// CSR build
// ---------------------------------------------------------------------------
__global__ void zero_int_kernel(int* p, int n) {
    int i = blockIdx.x * blockDim.x + threadIdx.x;
    if (i < n) p[i] = 0;
}

__global__ void hist_kernel(const int* __restrict__ tgt, int* __restrict__ deg, int e) {
    int i = blockIdx.x * blockDim.x + threadIdx.x;
    if (i < e) atomicAdd(&deg[tgt[i]], 1);
}

// Single-block exclusive scan over deg[n] -> rowptr[n+1], cursor[n].
__global__ void scan_kernel(const int* __restrict__ deg, int* __restrict__ rowptr,
                            int* __restrict__ cursor, int n) {
    __shared__ int sums[1024];
    int t = threadIdx.x;
    const int CH = (n + 1023) >> 10;   // chunk per thread
    int beg = t * CH;
    int endi = beg + CH; if (endi > n) endi = n;
    int s = 0;
    for (int i = beg; i < endi; ++i) s += deg[i];
    sums[t] = s;
    __syncthreads();
    // Hillis-Steele inclusive scan
    for (int off = 1; off < 1024; off <<= 1) {
        int v = (t >= off) ? sums[t - off] : 0;
        __syncthreads();
        sums[t] += v;
        __syncthreads();
    }
    int run = (t == 0) ? 0 : sums[t - 1];
    for (int i = beg; i < endi; ++i) {
        rowptr[i] = run;
        cursor[i] = run;
        run += deg[i];
    }
    if (t == 0) rowptr[n] = sums[1023];
}

__global__ void fill_kernel(const int* __restrict__ src, const int* __restrict__ tgt,
                            const float* __restrict__ ew, int* __restrict__ cursor,
                            int2* __restrict__ esw, int e) {
    int i = blockIdx.x * blockDim.x + threadIdx.x;
    if (i < e) {
        int p = atomicAdd(&cursor[tgt[i]], 1);
        esw[p] = make_int2(src[i], __float_as_int(ew[i]));
    }
}

// ---------------------------------------------------------------------------
// Dense GEMM with fused bias: C[M,N] = A[M,K] @ W[K,N] + b
// BM=128, BK=16, 256 threads, thread tile TM x 8.
// ---------------------------------------------------------------------------
template<int K, int N, int BN>
__global__ void __launch_bounds__(256)
gemm_bias_kernel(const float* __restrict__ A, const float* __restrict__ W,
                 const float* __restrict__ bias, float* __restrict__ C, int M) {
    constexpr int BM = 128, BK = 16, TN = 8;
    constexpr int COLT = BN / TN;          // 16 (BN=128) or 8 (BN=64)
    constexpr int ROWT = 256 / COLT;       // 16 or 32
    constexpr int TM   = BM / ROWT;        // 8 or 4
    constexpr int ALOADS = (BM * BK) / (4 * 256);   // 2
    constexpr int BLOADS = (BK * BN) / (4 * 256);   // 2 or 1

    __shared__ float As[BK][BM];
    __shared__ float Bs[BK][BN];

    const int tid  = threadIdx.x;
    const int row0 = blockIdx.x * BM;
    const int tr   = tid / COLT;
    const int tc   = tid % COLT;

    float acc[TM][TN];
#pragma unroll
    for (int i = 0; i < TM; ++i)
#pragma unroll
        for (int j = 0; j < TN; ++j) acc[i][j] = 0.0f;

    for (int kk = 0; kk < K; kk += BK) {
        // ---- load A tile (transposed into As[k][m]) ----
#pragma unroll
        for (int i = 0; i < ALOADS; ++i) {
            int lin = tid + i * 256;
            int r   = lin >> 2;          // BK/4 == 4
            int c4  = lin & 3;
            int grow = row0 + r;
            float4 v = make_float4(0.f, 0.f, 0.f, 0.f);
            if (grow < M)
                v = *(const float4*)&A[(size_t)grow * K + kk + c4 * 4];
            As[c4 * 4 + 0][r] = v.x;
            As[c4 * 4 + 1][r] = v.y;
            As[c4 * 4 + 2][r] = v.z;
            As[c4 * 4 + 3][r] = v.w;
        }
        // ---- load B tile ----
#pragma unroll
        for (int i = 0; i < BLOADS; ++i) {
            int lin = tid + i * 256;
            int r   = lin / (BN / 4);
            int c   = (lin % (BN / 4)) * 4;
            float4 v = make_float4(0.f, 0.f, 0.f, 0.f);
            if (c < N)
                v = *(const float4*)&W[(size_t)(kk + r) * N + c];
            *(float4*)&Bs[r][c] = v;
        }
        __syncthreads();

#pragma unroll
        for (int k = 0; k < BK; ++k) {
            float a[TM], b[TN];
#pragma unroll
            for (int i = 0; i < TM; i += 4) {
                float4 t = *(const float4*)&As[k][tr * TM + i];
                a[i] = t.x; a[i + 1] = t.y; a[i + 2] = t.z; a[i + 3] = t.w;
            }
#pragma unroll
            for (int j = 0; j < TN; j += 4) {
                float4 t = *(const float4*)&Bs[k][tc * TN + j];
                b[j] = t.x; b[j + 1] = t.y; b[j + 2] = t.z; b[j + 3] = t.w;
            }
#pragma unroll
            for (int i = 0; i < TM; ++i)
#pragma unroll
                for (int j = 0; j < TN; ++j)
                    acc[i][j] = fmaf(a[i], b[j], acc[i][j]);
        }
        __syncthreads();
    }

    // ---- epilogue: add bias, store ----
#pragma unroll
    for (int i = 0; i < TM; ++i) {
        int grow = row0 + tr * TM + i;
        if (grow >= M) continue;
#pragma unroll
        for (int j = 0; j < TN; j += 4) {
            int c = tc * TN + j;
            if (c + 3 < N) {
                float4 o;
                o.x = acc[i][j + 0] + bias[c + 0];
                o.y = acc[i][j + 1] + bias[c + 1];
                o.z = acc[i][j + 2] + bias[c + 2];
                o.w = acc[i][j + 3] + bias[c + 3];
                *(float4*)&C[(size_t)grow * N + c] = o;
            } else {
#pragma unroll
                for (int jj = 0; jj < 4; ++jj)
                    if (c + jj < N)
                        C[(size_t)grow * N + c + jj] = acc[i][j + jj] + bias[c + jj];
            }
        }
    }
}

// ---------------------------------------------------------------------------
// Aggregation (gather-CSR), F=128, warp per node, float4 per lane.
// MODE 0: relu(sum);  MODE 1: relu(sum) + res
// ---------------------------------------------------------------------------
template<int MODE>
__global__ void agg128_kernel(const float* __restrict__ h,
                              const int* __restrict__ rowptr,
                              const int2* __restrict__ esw,
                              const float* __restrict__ res,
                              float* __restrict__ out, int n) {
    int warp = (blockIdx.x * blockDim.x + threadIdx.x) >> 5;
    int lane = threadIdx.x & 31;
    if (warp >= n) return;
    int beg = rowptr[warp];
    int end = rowptr[warp + 1];

    const float4* h4 = (const float4*)h;
    float4 acc = make_float4(0.f, 0.f, 0.f, 0.f);

    int j = beg;
    // 2x unroll for memory-level parallelism
    for (; j + 1 < end; j += 2) {
        int2 sw0 = __ldg(&esw[j]);
        int2 sw1 = __ldg(&esw[j + 1]);
        float w0 = __int_as_float(sw0.y);
        float w1 = __int_as_float(sw1.y);
        float4 v0 = __ldg(&h4[(size_t)sw0.x * 32 + lane]);
        float4 v1 = __ldg(&h4[(size_t)sw1.x * 32 + lane]);
        acc.x = fmaf(v0.x, w0, acc.x); acc.y = fmaf(v0.y, w0, acc.y);
        acc.z = fmaf(v0.z, w0, acc.z); acc.w = fmaf(v0.w, w0, acc.w);
        acc.x = fmaf(v1.x, w1, acc.x); acc.y = fmaf(v1.y, w1, acc.y);
        acc.z = fmaf(v1.z, w1, acc.z); acc.w = fmaf(v1.w, w1, acc.w);
    }
    if (j < end) {
        int2 sw = __ldg(&esw[j]);
        float w = __int_as_float(sw.y);
        float4 v = __ldg(&h4[(size_t)sw.x * 32 + lane]);
        acc.x = fmaf(v.x, w, acc.x); acc.y = fmaf(v.y, w, acc.y);
        acc.z = fmaf(v.z, w, acc.z); acc.w = fmaf(v.w, w, acc.w);
    }

    acc.x = fmaxf(acc.x, 0.f); acc.y = fmaxf(acc.y, 0.f);
    acc.z = fmaxf(acc.z, 0.f); acc.w = fmaxf(acc.w, 0.f);
    if (MODE == 1) {
        float4 r = ((const float4*)res)[(size_t)warp * 32 + lane];
        acc.x += r.x; acc.y += r.y; acc.z += r.z; acc.w += r.w;
    }
    ((float4*)out)[(size_t)warp * 32 + lane] = acc;
}

// ---------------------------------------------------------------------------
// Final aggregation (F=40) fused with log_softmax; writes d_out directly.
// Warp per node; lane covers column lane, and (lane<8) column lane+32.
// ---------------------------------------------------------------------------
__global__ void agg40_lsm_kernel(const float* __restrict__ h,
                                 const int* __restrict__ rowptr,
                                 const int2* __restrict__ esw,
                                 float* __restrict__ out, int n) {
    int warp = (blockIdx.x * blockDim.x + threadIdx.x) >> 5;
    int lane = threadIdx.x & 31;
    if (warp >= n) return;
    int beg = rowptr[warp];
    int end = rowptr[warp + 1];

    float a0 = 0.f, a1 = 0.f;
    for (int j = beg; j < end; ++j) {
        int2 sw = __ldg(&esw[j]);
        float w = __int_as_float(sw.y);
        const float* hp = h + (size_t)sw.x * F_OUT;
        a0 = fmaf(__ldg(&hp[lane]), w, a0);
        if (lane < 8) a1 = fmaf(__ldg(&hp[32 + lane]), w, a1);
    }

    // log_softmax over the 40 values held by the warp
    float m = a0;
    if (lane < 8) m = fmaxf(m, a1);
#pragma unroll
    for (int o = 16; o > 0; o >>= 1)
        m = fmaxf(m, __shfl_xor_sync(0xffffffffu, m, o));

    float s = expf(a0 - m) + ((lane < 8) ? expf(a1 - m) : 0.f);
#pragma unroll
    for (int o = 16; o > 0; o >>= 1)
        s += __shfl_xor_sync(0xffffffffu, s, o);
    float lse = logf(s);

    out[(size_t)warp * F_OUT + lane] = a0 - m - lse;
    if (lane < 8)
        out[(size_t)warp * F_OUT + 32 + lane] = a1 - m - lse;
}

// ---------------------------------------------------------------------------
// Launch
// ---------------------------------------------------------------------------
extern "C" void kernel_launch(void* const* d_in, const int* in_sizes, int n_in,
                              void* d_out, int out_size) {
    const float* x   = (const float*)d_in[0];
    const int*   src = (const int*)  d_in[1];
    const int*   tgt = (const int*)  d_in[2];
    const float* ew  = (const float*)d_in[3];
    const float* W0  = (const float*)d_in[4];
    const float* b0  = (const float*)d_in[5];
    const float* W1  = (const float*)d_in[6];
    const float* b1  = (const float*)d_in[7];
    const float* W2  = (const float*)d_in[8];
    const float* b2  = (const float*)d_in[9];
    const float* W3  = (const float*)d_in[10];
    const float* b3  = (const float*)d_in[11];
    float* out = (float*)d_out;

    float *h, *x0, *xa, *xb;
    int *deg, *rowptr, *cursor;
    int2* esw;
    cudaGetSymbolAddress((void**)&h,      g_h);
    cudaGetSymbolAddress((void**)&x0,     g_x0);
    cudaGetSymbolAddress((void**)&xa,     g_xa);
    cudaGetSymbolAddress((void**)&xb,     g_xb);
    cudaGetSymbolAddress((void**)&deg,    g_deg);
    cudaGetSymbolAddress((void**)&rowptr, g_rowptr);
    cudaGetSymbolAddress((void**)&cursor, g_cursor);
    cudaGetSymbolAddress((void**)&esw,    g_esw);

    const int M = NNODES;
    const int E = NEDGES;

    // ---- CSR build (by target) ----
    zero_int_kernel<<<(M + 255) / 256, 256>>>(deg, M);
    hist_kernel<<<(E + 255) / 256, 256>>>(tgt, deg, E);
    scan_kernel<<<1, 1024>>>(deg, rowptr, cursor, M);
    fill_kernel<<<(E + 255) / 256, 256>>>(src, tgt, ew, cursor, esw, E);

    const int gemm_blocks = (M + 127) / 128;
    const int agg_blocks  = (M + 7) / 8;      // 8 warps per 256-thread block

    // ---- layer 0: x0 = relu(agg(x @ W0 + b0)) ----
    gemm_bias_kernel<F_IN, F_HID, 128><<<gemm_blocks, 256>>>(x, W0, b0, h, M);
    agg128_kernel<0><<<agg_blocks, 256>>>(h, rowptr, esw, nullptr, x0, M);

    // ---- layer 1: x1 = relu(agg(x0 @ W1 + b1)) ----
    gemm_bias_kernel<F_HID, F_HID, 128><<<gemm_blocks, 256>>>(x0, W1, b1, h, M);
    agg128_kernel<0><<<agg_blocks, 256>>>(h, rowptr, esw, nullptr, xa, M);

    // ---- layer 2: x2 = relu(agg(x1 @ W2 + b2)) + x0 ----
    gemm_bias_kernel<F_HID, F_HID, 128><<<gemm_blocks, 256>>>(xa, W2, b2, h, M);
    agg128_kernel<1><<<agg_blocks, 256>>>(h, rowptr, esw, x0, xb, M);

    // ---- layer 3: out = log_softmax(agg(x2 @ W3 + b3)) ----
    gemm_bias_kernel<F_HID, F_OUT, 64><<<gemm_blocks, 256>>>(xb, W3, b3, h, M);
    agg40_lsm_kernel<<<agg_blocks, 256>>>(h, rowptr, esw, out, M);
}